// round 4
// baseline (speedup 1.0000x reference)
#include <cuda_runtime.h>
#include <math.h>

#define Bb 64
#define Tt 50000
#define Cc 4
#define MS 4
#define Dd 160
#define PP 25
#define LL 2000          // T / PP
#define KE 25
#define KB 9
#define KP 9
#define TILE 1000        // multiple of PP
#define NT (Tt / TILE)   // 50
#define HSIZE (Bb * LL * Dd)   // 20,480,000 floats of h
#define KK 100           // MS*PP GEMM depth

// scratch: xs laid out as GEMM rows [b*L + l][m*25 + p]
__device__ float g_xs[(size_t)Bb * LL * KK];

__device__ __forceinline__ float gelu_exact(float v) {
    return 0.5f * v * (1.0f + erff(v * 0.70710678118654752f));
}
__device__ __forceinline__ float softplus_f(float v) {
    return fmaxf(v, 0.0f) + log1pf(expf(-fabsf(v)));
}

typedef unsigned long long ull;

__device__ __forceinline__ ull ffma2(ull a, ull b, ull c) {
    ull d;
    asm("fma.rn.f32x2 %0, %1, %2, %3;" : "=l"(d) : "l"(a), "l"(b), "l"(c));
    return d;
}
union F4U { float4 v; ull u[2]; };
union UF2 { ull u; float2 f; };

// ---------------------------------------------------------------------------
// Kernel A: fused front pipeline (unchanged from round 2)
// ---------------------------------------------------------------------------
__global__ __launch_bounds__(256) void kernelA(
    const float* __restrict__ X, const float* __restrict__ Mv,
    const float* __restrict__ w_env, const float* __restrict__ w_burst,
    const float* __restrict__ syn, const float* __restrict__ w_dw,
    const float* __restrict__ w_pw, float* __restrict__ out_mpatch)
{
    __shared__ __align__(16) float sx[Cc][TILE + 40];
    __shared__ float sS0[MS][TILE + 8];
    __shared__ uchar4 smask[TILE];
    __shared__ unsigned char smt[TILE];
    __shared__ float sW[MS][Cc];
    __shared__ float sWe[Cc][KE], sWb[Cc][KB], sWd[MS][KP], sPW[MS][MS];

    const int tid  = threadIdx.x;
    const int tile = blockIdx.x;
    const int b    = blockIdx.y;
    const int t0   = tile * TILE;

    for (int i = tid; i < Cc * KE; i += 256) sWe[i / KE][i % KE] = w_env[i];
    for (int i = tid; i < Cc * KB; i += 256) sWb[i / KB][i % KB] = w_burst[i];
    for (int i = tid; i < MS * KP; i += 256) sWd[i / KP][i % KP] = w_dw[i];
    for (int i = tid; i < MS * MS; i += 256) sPW[i / MS][i % MS] = w_pw[i];
    if (tid < MS) {
        float v0 = softplus_f(syn[tid * Cc + 0]);
        float v1 = softplus_f(syn[tid * Cc + 1]);
        float v2 = softplus_f(syn[tid * Cc + 2]);
        float v3 = softplus_f(syn[tid * Cc + 3]);
        float s  = fmaxf(v0 + v1 + v2 + v3, 1e-6f);
        float inv = 1.0f / s;
        sW[tid][0] = v0 * inv; sW[tid][1] = v1 * inv;
        sW[tid][2] = v2 * inv; sW[tid][3] = v3 * inv;
    }

    const float4* X4 = (const float4*)(X + (size_t)b * Tt * Cc);
    const float4* M4 = (const float4*)(Mv + (size_t)b * Tt * Cc);
    for (int i = tid; i < TILE + 33; i += 256) {
        int t = t0 - 16 + i;
        float4 xv = {0.f, 0.f, 0.f, 0.f};
        uchar4 mk = {0, 0, 0, 0};
        if (t >= 0 && t < Tt) {
            float4 a = X4[t], m = M4[t];
            xv.x = a.x * m.x; xv.y = a.y * m.y; xv.z = a.z * m.z; xv.w = a.w * m.w;
            mk.x = (m.x > 0.f); mk.y = (m.y > 0.f); mk.z = (m.z > 0.f); mk.w = (m.w > 0.f);
        }
        sx[0][i] = xv.x; sx[1][i] = xv.y; sx[2][i] = xv.z; sx[3][i] = xv.w;
        int j = i - 16;
        if (j >= 0 && j < TILE) smask[j] = mk;
    }
    __syncthreads();

    if (tid < 252) {
        const int j0 = tid * 4;
        float s0a[MS][4];
        #pragma unroll
        for (int m = 0; m < MS; m++)
            #pragma unroll
            for (int p = 0; p < 4; p++) s0a[m][p] = 0.f;

        #pragma unroll
        for (int c = 0; c < Cc; c++) {
            float win[28];
            #pragma unroll
            for (int u = 0; u < 7; u++) {
                float4 v = *(const float4*)&sx[c][j0 + 4 * u];
                win[4*u] = v.x; win[4*u+1] = v.y; win[4*u+2] = v.z; win[4*u+3] = v.w;
            }
            float dabs[12];
            #pragma unroll
            for (int u = 8; u < 20; u++) {
                int tg = t0 - 16 + j0 + u;
                float d = win[u] - win[u - 1];
                dabs[u - 8] = (tg >= 1 && tg < Tt) ? fabsf(d) : 0.f;
            }
            float env[4] = {0.f, 0.f, 0.f, 0.f};
            float bur[4] = {0.f, 0.f, 0.f, 0.f};
            #pragma unroll
            for (int k = 0; k < KE; k++) {
                float w = sWe[c][k];
                env[0] += fabsf(win[k    ]) * w;
                env[1] += fabsf(win[k + 1]) * w;
                env[2] += fabsf(win[k + 2]) * w;
                env[3] += fabsf(win[k + 3]) * w;
            }
            #pragma unroll
            for (int k = 0; k < KB; k++) {
                float w = sWb[c][k];
                bur[0] += dabs[k    ] * w;
                bur[1] += dabs[k + 1] * w;
                bur[2] += dabs[k + 2] * w;
                bur[3] += dabs[k + 3] * w;
            }
            #pragma unroll
            for (int p = 0; p < 4; p++) {
                float xmv = 0.9f * env[p] + 0.6f * bur[p] + 0.2f * win[p + 12];
                #pragma unroll
                for (int m = 0; m < MS; m++) s0a[m][p] += sW[m][c] * xmv;
            }
        }
        #pragma unroll
        for (int p = 0; p < 4; p++) {
            int j  = j0 + p;
            int tp = t0 - 4 + j;
            bool valid = (tp >= 0 && tp < Tt);
            #pragma unroll
            for (int m = 0; m < MS; m++)
                sS0[m][j] = valid ? s0a[m][p] : 0.f;
        }
    }
    __syncthreads();

    for (int i = tid; i < TILE; i += 256) {
        float S1[MS];
        #pragma unroll
        for (int m = 0; m < MS; m++) {
            float a = 0.f;
            #pragma unroll
            for (int k = 0; k < KP; k++) a += sS0[m][i + k] * sWd[m][k];
            S1[m] = gelu_exact(a);
        }
        uchar4 mk = smask[i];
        float mf0 = (float)mk.x, mf1 = (float)mk.y, mf2 = (float)mk.z, mf3 = (float)mk.w;
        int t = t0 + i;
        int l = t / PP, p = t - l * PP;
        float* dst = &g_xs[((size_t)b * LL + l) * KK + p];
        float smsum = 0.f;
        #pragma unroll
        for (int o = 0; o < MS; o++) {
            float a  = sPW[o][0]*S1[0] + sPW[o][1]*S1[1] + sPW[o][2]*S1[2] + sPW[o][3]*S1[3];
            float s2 = gelu_exact(a);
            float sm = sW[o][0]*mf0 + sW[o][1]*mf1 + sW[o][2]*mf2 + sW[o][3]*mf3;
            sm = fminf(fmaxf(sm, 0.f), 1.f);
            smsum += sm;
            dst[o * PP] = s2 * sm;
        }
        smt[i] = (smsum > 0.f) ? 1 : 0;
    }
    __syncthreads();

    if (tid < TILE / PP) {
        int s = 0;
        #pragma unroll
        for (int p = 0; p < PP; p++) s += smt[tid * PP + p];
        out_mpatch[(size_t)b * LL + tile * (TILE / PP) + tid] = (s >= 3) ? 1.f : 0.f;
    }
}

// ---------------------------------------------------------------------------
// Kernel B v3: [128000 x 100] @ [100 x 160] + fused LayerNorm
//   FFMA2 paired over K (even/odd) -> zero broadcast instructions.
//   block: 64 rows x 160 cols, 320 threads (16 rg x 20 dg),
//   thread tile: 4 rows x 8 cols (4 col-pairs at d = dg*2 + 40j).
//   K chunked by 50 (25 k-pairs). smem k-pair-major float2 (as ull).
// ---------------------------------------------------------------------------
#define RB 64
#define NK2 25            // k-pairs per chunk
#define AS 66             // sA2 row stride (ull), even for 16B-aligned LDS.128
#define WS 162            // sW2 row stride (ull)
#define SA_SIZE (NK2 * AS)            // 1650 ull
#define SMEMB_ULL (SA_SIZE + NK2 * WS) // 1650 + 4050 = 5700 ull = 45.6 KB

__global__ __launch_bounds__(320, 2) void kernelB(
    const float* __restrict__ wproj, const float* __restrict__ gamma,
    const float* __restrict__ beta, float* __restrict__ out)
{
    __shared__ __align__(16) ull smem[SMEMB_ULL];
    __shared__ float sMu[RB], sRs[RB];
    ull* sA2 = smem;                  // [NK2][AS]  (k2-major, row contiguous)
    ull* sW2 = smem + SA_SIZE;        // [NK2][WS]  (k2-major, d contiguous)

    const int tid  = threadIdx.x;
    const int Row0 = blockIdx.x * RB;
    const int dg = tid % 20, rg = tid / 20;
    const int r0 = rg * 4;            // 4 rows
    // 8 cols: d = dg*2 + 40*j and d+1, j = 0..3

    ull acc[4][8];
    #pragma unroll
    for (int r = 0; r < 4; r++)
        #pragma unroll
        for (int c = 0; c < 8; c++) acc[r][c] = 0ULL;

    for (int kc = 0; kc < 2; kc++) {
        const int kb = kc * 50;
        __syncthreads();
        // A: g_xs[row][kb + 2*k2 .. +1] (float2) -> sA2[k2][row]
        for (int i = tid; i < RB * NK2; i += 320) {
            int row = i / NK2, k2 = i - row * NK2;
            const float2 v = *(const float2*)&g_xs[(size_t)(Row0 + row) * KK + kb + 2 * k2];
            UF2 u; u.f = v;
            sA2[k2 * AS + row] = u.u;
        }
        // W: wproj[d][kb + 2*k2 .. +1] -> sW2[k2][d]
        for (int i = tid; i < Dd * NK2; i += 320) {
            int d = i / NK2, k2 = i - d * NK2;
            const float2 v = *(const float2*)&wproj[d * KK + kb + 2 * k2];
            UF2 u; u.f = v;
            sW2[k2 * WS + d] = u.u;
        }
        __syncthreads();

        #pragma unroll 5
        for (int k2 = 0; k2 < NK2; k2++) {
            F4U a01, a23, w[4];
            a01.v = *(const float4*)&sA2[k2 * AS + r0];
            a23.v = *(const float4*)&sA2[k2 * AS + r0 + 2];
            #pragma unroll
            for (int j = 0; j < 4; j++)
                w[j].v = *(const float4*)&sW2[k2 * WS + dg * 2 + 40 * j];
            ull ar[4] = {a01.u[0], a01.u[1], a23.u[0], a23.u[1]};
            #pragma unroll
            for (int r = 0; r < 4; r++) {
                #pragma unroll
                for (int j = 0; j < 4; j++) {
                    acc[r][2*j]   = ffma2(ar[r], w[j].u[0], acc[r][2*j]);
                    acc[r][2*j+1] = ffma2(ar[r], w[j].u[1], acc[r][2*j+1]);
                }
            }
        }
    }

    // ---- collapse k-pairs: h = acc.x + acc.y ----
    float h[4][8];
    #pragma unroll
    for (int r = 0; r < 4; r++)
        #pragma unroll
        for (int c = 0; c < 8; c++) {
            UF2 u; u.u = acc[r][c];
            h[r][c] = u.f.x + u.f.y;
        }
    __syncthreads();

    // ---- fused LayerNorm ----
    float* sSum = (float*)smem;             // [RB][20]
    float* sSq  = (float*)smem + RB * 20;   // [RB][20]
    #pragma unroll
    for (int r = 0; r < 4; r++) {
        float s = 0.f, q = 0.f;
        #pragma unroll
        for (int c = 0; c < 8; c++) { s += h[r][c]; q += h[r][c] * h[r][c]; }
        sSum[(r0 + r) * 20 + dg] = s;
        sSq [(r0 + r) * 20 + dg] = q;
    }
    __syncthreads();
    if (tid < RB) {
        float s = 0.f, q = 0.f;
        #pragma unroll
        for (int j = 0; j < 20; j++) {
            s += sSum[tid * 20 + j];
            q += sSq [tid * 20 + j];
        }
        float mu  = s * (1.0f / Dd);
        float var = q * (1.0f / Dd) - mu * mu;
        sMu[tid] = mu;
        sRs[tid] = rsqrtf(var + 1e-5f);
    }
    __syncthreads();

    float2 gm[4], bt[4];
    #pragma unroll
    for (int j = 0; j < 4; j++) {
        int d = dg * 2 + 40 * j;
        gm[j] = *(const float2*)&gamma[d];
        bt[j] = *(const float2*)&beta[d];
    }

    #pragma unroll
    for (int r = 0; r < 4; r++) {
        float mu = sMu[r0 + r], rs = sRs[r0 + r];
        float* dst = out + (size_t)(Row0 + r0 + r) * Dd;
        #pragma unroll
        for (int j = 0; j < 4; j++) {
            int d = dg * 2 + 40 * j;
            float2 v;
            v.x = (h[r][2*j]   - mu) * rs * gm[j].x + bt[j].x;
            v.y = (h[r][2*j+1] - mu) * rs * gm[j].y + bt[j].y;
            *(float2*)(dst + d) = v;
        }
    }
}

// ---------------------------------------------------------------------------
extern "C" void kernel_launch(void* const* d_in, const int* in_sizes, int n_in,
                              void* d_out, int out_size)
{
    const float* X      = (const float*)d_in[0];
    const float* M      = (const float*)d_in[1];
    const float* w_env  = (const float*)d_in[2];
    const float* w_bur  = (const float*)d_in[3];
    const float* syn    = (const float*)d_in[4];
    const float* w_dw   = (const float*)d_in[5];
    const float* w_pw   = (const float*)d_in[6];
    const float* w_proj = (const float*)d_in[7];
    const float* gamma  = (const float*)d_in[8];
    const float* beta   = (const float*)d_in[9];
    float* out = (float*)d_out;

    dim3 gA(NT, Bb);
    kernelA<<<gA, 256>>>(X, M, w_env, w_bur, syn, w_dw, w_pw, out + HSIZE);
    kernelB<<<(Bb * LL) / RB, 320>>>(w_proj, gamma, beta, out);
}